// round 15
// baseline (speedup 1.0000x reference)
#include <cuda_runtime.h>

namespace {
constexpr int T_STEPS = 1000;
constexpr int B       = 256;
constexpr int IN_DIM  = 3;
constexpr int H       = 512;
constexpr int OUT_DIM = 2;
constexpr int NT      = 512;          // one thread per neuron
constexpr int NWARP   = NT / 32;      // 16
constexpr int TAIL    = 10;           // readout window
}

__global__ __launch_bounds__(NT)
void snn_fused_kernel(const float* __restrict__ x,
                      const float* __restrict__ W1,
                      const float* __restrict__ W2,
                      float* __restrict__ out,
                      long long avg_off)
{
    __shared__ float  tailbuf[TAIL][2][NWARP];  // per-t, per-warp partial W2 dots
    __shared__ float  sg[2][TAIL];              // per-t sigmoid values

    const int b   = blockIdx.x;
    const int tid = threadIdx.x;

    // This thread's neuron weights
    const int h = tid;
    const float w10 = W1[(size_t)h * IN_DIM + 0];
    const float w11 = W1[(size_t)h * IN_DIM + 1];
    const float w12 = W1[(size_t)h * IN_DIM + 2];
    const float w2r0 = W2[h];        // W2[0, h]
    const float w2r1 = W2[H + h];    // W2[1, h]

    float mem = 0.0f;
    bool  p   = false;               // reset predicate = (mem_prev > 1) = previous spike
    float* outp = out + (size_t)b * H + h;
    const float* xp = x + (size_t)b * IN_DIM;   // x[t][b][:] at xp + t*B*IN_DIM

    // ---- main recurrence: 990 steps, no staging, no barriers.
    //      x access is a CTA-wide broadcast: first warp misses to L2 (resident),
    //      trailing warps hit L1. Stores start immediately; drift spreads them. ----
#pragma unroll 10
    for (int t = 0; t < T_STEPS - TAIL; ++t) {
        const float* xt = xp + (size_t)t * B * IN_DIM;
        float x0 = __ldg(xt + 0);
        float x1 = __ldg(xt + 1);
        float x2 = __ldg(xt + 2);
        // cur = x0*w0 (+fma) x1*w1 (+fma) x2*w2  (k-ascending fma chain)
        float cur = __fmaf_rn(x2, w12, __fmaf_rn(x1, w11, __fmul_rn(x0, w10)));
        // mem_new = (0.8*mem + cur) * (1 - reset), reset from PREVIOUS mem (== prev spike)
        float vm = __fadd_rn(__fmul_rn(0.8f, mem), cur);
        float mn = p ? 0.0f : vm;
        p   = (mn > 1.0f);                 // spike AND next step's reset
        mem = mn;
        __stwt(outp, p ? 1.0f : 0.0f);     // write-through: never read, no L2 dirty debt
        outp += B * H;
    }

    // ---- last 10 steps: recurrence + barrier-free partial recording ----
    const int lane = tid & 31;
    const int warp = tid >> 5;
#pragma unroll
    for (int ti = 0; ti < TAIL; ++ti) {
        const int t = T_STEPS - TAIL + ti;
        const float* xt = xp + (size_t)t * B * IN_DIM;
        float x0 = __ldg(xt + 0);
        float x1 = __ldg(xt + 1);
        float x2 = __ldg(xt + 2);
        float cur = __fmaf_rn(x2, w12, __fmaf_rn(x1, w11, __fmul_rn(x0, w10)));
        float vm = __fadd_rn(__fmul_rn(0.8f, mem), cur);
        float mn = p ? 0.0f : vm;
        p   = (mn > 1.0f);
        mem = mn;
        float s = p ? 1.0f : 0.0f;
        __stwt(outp, s);
        outp += B * H;

        float p0 = s * w2r0;
        float p1 = s * w2r1;
#pragma unroll
        for (int off = 16; off > 0; off >>= 1) {
            p0 += __shfl_down_sync(0xffffffffu, p0, off);
            p1 += __shfl_down_sync(0xffffffffu, p1, off);
        }
        if (lane == 0) { tailbuf[ti][0][warp] = p0; tailbuf[ti][1][warp] = p1; }
    }
    __syncthreads();   // all tail partials recorded

    // threads 0..9 each reduce one timestep and apply sigmoid
    if (tid < TAIL) {
        float d0 = 0.0f, d1 = 0.0f;
#pragma unroll
        for (int w = 0; w < NWARP; ++w) { d0 += tailbuf[tid][0][w]; d1 += tailbuf[tid][1][w]; }
        sg[0][tid] = 1.0f / (1.0f + expf(-d0));
        sg[1][tid] = 1.0f / (1.0f + expf(-d1));
    }
    __syncthreads();

    if (tid == 0) {
        float a0 = 0.0f, a1 = 0.0f;
#pragma unroll
        for (int ti = 0; ti < TAIL; ++ti) { a0 += sg[0][ti]; a1 += sg[1][ti]; }
        float* ao = out + avg_off + (size_t)b * OUT_DIM;
        ao[0] = a0 * 0.1f;
        ao[1] = a1 * 0.1f;
    }
}

extern "C" void kernel_launch(void* const* d_in, const int* in_sizes, int n_in,
                              void* d_out, int out_size) {
    const float* x  = (const float*)d_in[0];   // x_seq [1000, 256, 3]
    const float* W1 = (const float*)d_in[1];   // [512, 3]
    const float* W2 = (const float*)d_in[2];   // [2, 512]
    float* out = (float*)d_out;
    long long avg_off = (long long)out_size - (long long)(B * OUT_DIM);
    snn_fused_kernel<<<B, NT>>>(x, W1, W2, out, avg_off);
}

// round 16
// speedup vs baseline: 2.7255x; 2.7255x over previous
#include <cuda_runtime.h>

namespace {
constexpr int T_STEPS = 1000;
constexpr int B       = 256;
constexpr int IN_DIM  = 3;
constexpr int H       = 512;
constexpr int OUT_DIM = 2;
constexpr int NT      = 512;          // one thread per neuron
constexpr int NWARP   = NT / 32;      // 16
constexpr int TAIL    = 10;           // readout window
constexpr int CT      = 200;          // timesteps per staging chunk
constexpr int NCHUNK  = T_STEPS / CT; // 5
static_assert(T_STEPS % CT == 0, "chunks must tile T exactly");
static_assert(CT <= NT, "one staging thread per timestep");
}

__global__ __launch_bounds__(NT)
void snn_fused_kernel(const float* __restrict__ x,
                      const float* __restrict__ W1,
                      const float* __restrict__ W2,
                      float* __restrict__ out,
                      long long avg_off)
{
    __shared__ float4 xs[T_STEPS];              // 16 KB input stage (pipelined fill)
    __shared__ float  tailbuf[TAIL][2][NWARP];  // per-t, per-warp partial W2 dots
    __shared__ float  sg[2][TAIL];              // per-t sigmoid values

    const int b   = blockIdx.x;
    const int tid = threadIdx.x;

    // This thread's neuron weights
    const int h = tid;
    const float w10 = W1[(size_t)h * IN_DIM + 0];
    const float w11 = W1[(size_t)h * IN_DIM + 1];
    const float w12 = W1[(size_t)h * IN_DIM + 2];
    const float w2r0 = W2[h];        // W2[0, h]
    const float w2r1 = W2[H + h];    // W2[1, h]

    // ---- prologue: stage ONLY chunk 0 (1/5 of the old gather) ----
    if (tid < CT) {
        const float* xp = x + ((size_t)tid * B + b) * IN_DIM;
        xs[tid] = make_float4(xp[0], xp[1], xp[2], 0.0f);
    }
    __syncthreads();

    float mem = 0.0f;
    bool  p   = false;               // reset predicate = (mem_prev > 1) = previous spike
    float* outp = out + (size_t)b * H + h;

    // ---- main recurrence: 5 chunks; next chunk's gather hidden under compute ----
#pragma unroll
    for (int c = 0; c < NCHUNK; ++c) {
        // issue next chunk's loads now; results consumed only at the STS below
        float pf0 = 0.0f, pf1 = 0.0f, pf2 = 0.0f;
        const bool do_pf = (tid < CT) && (c + 1 < NCHUNK);
        const int  tnext = (c + 1) * CT + tid;
        if (do_pf) {
            const float* xp = x + ((size_t)tnext * B + b) * IN_DIM;
            pf0 = xp[0]; pf1 = xp[1]; pf2 = xp[2];
        }

        const int tend = (c == NCHUNK - 1) ? (T_STEPS - TAIL) : (c + 1) * CT;
#pragma unroll 10
        for (int t = c * CT; t < tend; ++t) {
            const float4 xv = xs[t];
            // cur = x0*w0 (+fma) x1*w1 (+fma) x2*w2  (k-ascending fma chain)
            float cur = __fmaf_rn(xv.z, w12,
                        __fmaf_rn(xv.y, w11,
                        __fmul_rn(xv.x, w10)));
            // mem_new = (0.8*mem + cur) * (1 - reset), reset from PREVIOUS mem
            float vm = __fadd_rn(__fmul_rn(0.8f, mem), cur);
            float mn = p ? 0.0f : vm;
            p   = (mn > 1.0f);                 // spike AND next step's reset
            mem = mn;
            __stwt(outp, p ? 1.0f : 0.0f);     // write-through: never read again
            outp += B * H;
        }

        if (do_pf) xs[tnext] = make_float4(pf0, pf1, pf2, 0.0f);
        if (c + 1 < NCHUNK) __syncthreads();   // publish next chunk
    }

    // ---- last 10 steps (within chunk 4, already staged): barrier-free recording ----
    const int lane = tid & 31;
    const int warp = tid >> 5;
#pragma unroll
    for (int ti = 0; ti < TAIL; ++ti) {
        const int t = T_STEPS - TAIL + ti;
        const float4 xv = xs[t];
        float cur = __fmaf_rn(xv.z, w12,
                    __fmaf_rn(xv.y, w11,
                    __fmul_rn(xv.x, w10)));
        float vm = __fadd_rn(__fmul_rn(0.8f, mem), cur);
        float mn = p ? 0.0f : vm;
        p   = (mn > 1.0f);
        mem = mn;
        float s = p ? 1.0f : 0.0f;
        __stwt(outp, s);
        outp += B * H;

        float p0 = s * w2r0;
        float p1 = s * w2r1;
#pragma unroll
        for (int off = 16; off > 0; off >>= 1) {
            p0 += __shfl_down_sync(0xffffffffu, p0, off);
            p1 += __shfl_down_sync(0xffffffffu, p1, off);
        }
        if (lane == 0) { tailbuf[ti][0][warp] = p0; tailbuf[ti][1][warp] = p1; }
    }
    __syncthreads();   // all tail partials recorded

    // threads 0..9 each reduce one timestep and apply sigmoid
    if (tid < TAIL) {
        float d0 = 0.0f, d1 = 0.0f;
#pragma unroll
        for (int w = 0; w < NWARP; ++w) { d0 += tailbuf[tid][0][w]; d1 += tailbuf[tid][1][w]; }
        sg[0][tid] = 1.0f / (1.0f + expf(-d0));
        sg[1][tid] = 1.0f / (1.0f + expf(-d1));
    }
    __syncthreads();

    if (tid == 0) {
        float a0 = 0.0f, a1 = 0.0f;
#pragma unroll
        for (int ti = 0; ti < TAIL; ++ti) { a0 += sg[0][ti]; a1 += sg[1][ti]; }
        float* ao = out + avg_off + (size_t)b * OUT_DIM;
        ao[0] = a0 * 0.1f;
        ao[1] = a1 * 0.1f;
    }
}

extern "C" void kernel_launch(void* const* d_in, const int* in_sizes, int n_in,
                              void* d_out, int out_size) {
    const float* x  = (const float*)d_in[0];   // x_seq [1000, 256, 3]
    const float* W1 = (const float*)d_in[1];   // [512, 3]
    const float* W2 = (const float*)d_in[2];   // [2, 512]
    float* out = (float*)d_out;
    long long avg_off = (long long)out_size - (long long)(B * OUT_DIM);
    snn_fused_kernel<<<B, NT>>>(x, W1, W2, out, avg_off);
}